// round 16
// baseline (speedup 1.0000x reference)
#include <cuda_runtime.h>

static constexpr int B = 4096;
static constexpr int K = 1024;
static constexpr int C = 10;
static constexpr int M = 19;

// Block = 32 b x (KBLK=256) k, 256 threads, KSPLIT=4 -> grid (128,4)=512.
// Hot loop: stage 32k x 32b idx tiles (coalesced full lines), then warp w
// EXCLUSIVELY owns b-columns {w, w+8, w+16, w+24}: lanes = 32 k-samples of one
// b; __match_any_sync aggregates equal cells; leader does NON-ATOMIC
// cnt += popc  (single-writer-warp + single-leader-lane => race-free).
static constexpr int NB      = 32;
static constexpr int NW      = 8;
static constexpr int THREADS = NW * 32;           // 256
static constexpr int KSPLIT  = 4;
static constexpr int KBLK    = K / KSPLIT;        // 256
static constexpr int TILE    = 32;                // k per tile
static constexpr int NTILE   = KBLK / TILE;       // 8

static constexpr int CSTR    = 101;               // cnt row stride

__device__ float g_scratch[B * M];    // zero-init; re-zeroed by finishing block
__device__ int   g_ticket[B / NB];    // zero-init; reset by finishing block

__global__ __launch_bounds__(THREADS)
void ised_kernel(const float* __restrict__ x1,
                 const float* __restrict__ x2,
                 const int*   __restrict__ idx1,
                 const int*   __restrict__ idx2,
                 float*       __restrict__ out)
{
    __shared__ int      s1[TILE * 33];        // staged idx1 tile [k][b], pad 33
    __shared__ int      s2[TILE * 33];        // staged idx2 tile
    __shared__ unsigned cnt[NB * CSTR];       // per-b 100-cell histogram
    __shared__ float    xs1[NB][C];
    __shared__ float    xs2[NB][C];
    __shared__ float    rowsum[NB][M + 1];
    __shared__ int      s_last;

    const int tid  = threadIdx.x;
    const int lane = tid & 31;
    const int w    = tid >> 5;
    const int b0   = blockIdx.x * NB;
    const int k0   = blockIdx.y * KBLK;

    // ---- Zero histogram; stage x rows ----
    for (int e = tid; e < NB * CSTR; e += THREADS) {
        cnt[e] = 0u;
    }
    for (int e = tid; e < NB * C; e += THREADS) {
        const int bl = e / C;
        const int i  = e - bl * C;
        xs1[bl][i] = __ldg(&x1[(b0 + bl) * C + i]);
        xs2[bl][i] = __ldg(&x2[(b0 + bl) * C + i]);
    }
    __syncthreads();

    // ---- Hot loop over k-tiles ----
    for (int t = 0; t < NTILE; t++) {
        const int kb = k0 + t * TILE;

        // Stage: warp r-rows, coalesced 128B lines
        for (int e = tid; e < TILE * 32; e += THREADS) {
            const int r = e >> 5;
            const int c = e & 31;
            s1[r * 33 + c] = __ldg(&idx1[(size_t)(kb + r) * B + b0 + c]);
            s2[r * 33 + c] = __ldg(&idx2[(size_t)(kb + r) * B + b0 + c]);
        }
        __syncthreads();

        // Process: warp w owns columns w, w+8, w+16, w+24 (k-per-lane)
        #pragma unroll
        for (int q = 0; q < 4; q++) {
            const int cb   = w + q * NW;
            const int i1   = s1[lane * 33 + cb];   // banks (lane+cb)%32: clean
            const int i2   = s2[lane * 33 + cb];
            const int cell = i1 * 10 + i2;
            const unsigned mask = __match_any_sync(0xffffffffu, cell);
            if ((mask & ((1u << lane) - 1u)) == 0u) {      // leader lane
                cnt[cb * CSTR + cell] += __popc(mask);     // non-atomic, race-free
            }
        }
        __syncthreads();
    }

    // ---- Epilogue: result[b][m] = sum_{i+j=m} xs1[i]*xs2[j]*cnt[i,j] ----
    for (int e = tid; e < NB * M; e += THREADS) {
        const int bl  = e & (NB - 1);
        const int m   = e >> 5;
        const int ilo = (m > 9) ? (m - 9) : 0;
        const int ihi = (m < 9) ? m : 9;
        float v = 0.0f;
        for (int i = ilo; i <= ihi; i++) {
            const int j = m - i;
            v += xs1[bl][i] * xs2[bl][j] *
                 (float)cnt[bl * CSTR + i * 10 + j];
        }
        atomicAdd(&g_scratch[(b0 + bl) * M + m], v);
    }

    // ---- Ticket: last KSPLIT-block for this row-group finishes the rows ----
    __threadfence();
    __syncthreads();
    if (tid == 0) {
        s_last = (atomicAdd(&g_ticket[blockIdx.x], 1) == KSPLIT - 1);
    }
    __syncthreads();
    if (!s_last) return;

    for (int e = tid; e < NB * M; e += THREADS) {
        const int bl = e & (NB - 1);
        const int m  = e >> 5;
        rowsum[bl][m] = __ldcg(&g_scratch[(b0 + bl) * M + m]);
    }
    __syncthreads();

    if (tid < NB) {
        float sq = 0.0f;
        #pragma unroll
        for (int m = 0; m < M; m++) {
            const float v = rowsum[tid][m];
            sq += v * v;
        }
        rowsum[tid][M] = 1.0f / fmaxf(sqrtf(sq), 1e-12f);
    }
    __syncthreads();

    for (int e = tid; e < NB * M; e += THREADS) {
        const int bl = e & (NB - 1);
        const int m  = e >> 5;
        out[(size_t)(b0 + bl) * M + m] = rowsum[bl][m] * rowsum[bl][M];
        __stcg(&g_scratch[(b0 + bl) * M + m], 0.0f);   // reset for next replay
    }
    if (tid == 0) {
        g_ticket[blockIdx.x] = 0;
    }
}

extern "C" void kernel_launch(void* const* d_in, const int* in_sizes, int n_in,
                              void* d_out, int out_size)
{
    const float* x1   = (const float*)d_in[0];   // [B, C]
    const float* x2   = (const float*)d_in[1];   // [B, C]
    const int*   idx1 = (const int*)d_in[2];     // [K, B]
    const int*   idx2 = (const int*)d_in[3];     // [K, B]
    float*       out  = (float*)d_out;           // [B, M]

    (void)in_sizes; (void)n_in; (void)out_size;

    dim3 grid(B / NB, KSPLIT);
    ised_kernel<<<grid, THREADS>>>(x1, x2, idx1, idx2, out);
}

// round 17
// speedup vs baseline: 1.3180x; 1.3180x over previous
#include <cuda_runtime.h>

static constexpr int B = 4096;
static constexpr int K = 1024;
static constexpr int C = 10;
static constexpr int M = 19;

// Block = 32 b x KBLK k, 256 threads, KSPLIT=4 -> grid (128,4)=512.
// Stage 32k x 32b tiles; warp w owns b-cols {4w..4w+3}; per col: 4+4 bit-slice
// ballots -> per-lane cell masks -> joint counts via popc(m1 & m2) into
// REGISTER accumulators (no atomics, no match).
static constexpr int NB      = 32;
static constexpr int NW      = 8;
static constexpr int THREADS = NW * 32;           // 256
static constexpr int KSPLIT  = 4;
static constexpr int KBLK    = K / KSPLIT;        // 256
static constexpr int TILE    = 32;
static constexpr int NTILE   = KBLK / TILE;       // 8

static constexpr int CSTR    = 101;
static constexpr int MROW    = 21;                // mask words per col (20 + pad)
static constexpr int MWARP   = 4 * MROW;          // 84
static constexpr int NUNIT   = 13;                // 400 units / 32 lanes, padded

__device__ float g_scratch[B * M];    // zero-init; re-zeroed by finishing block
__device__ int   g_ticket[B / NB];    // zero-init; reset by finishing block

__global__ __launch_bounds__(THREADS)
void ised_kernel(const float* __restrict__ x1,
                 const float* __restrict__ x2,
                 const int*   __restrict__ idx1,
                 const int*   __restrict__ idx2,
                 float*       __restrict__ out)
{
    __shared__ int      s1[TILE * 33];            // staged idx1 [k][b]
    __shared__ int      s2[TILE * 33];
    __shared__ unsigned masks[NW * MWARP];        // per-warp mask scratch
    __shared__ unsigned cnt[NB * CSTR];           // final per-b histograms
    __shared__ float    xs1[NB][C];
    __shared__ float    xs2[NB][C];
    __shared__ float    rowsum[NB][M + 1];
    __shared__ int      s_last;

    const int tid  = threadIdx.x;
    const int lane = tid & 31;
    const int w    = tid >> 5;
    const int b0   = blockIdx.x * NB;
    const int k0   = blockIdx.y * KBLK;

    // ---- Stage x rows ----
    for (int e = tid; e < NB * C; e += THREADS) {
        const int bl = e / C;
        const int i  = e - bl * C;
        xs1[bl][i] = __ldg(&x1[(b0 + bl) * C + i]);
        xs2[bl][i] = __ldg(&x2[(b0 + bl) * C + i]);
    }

    // ---- Per-lane pair-unit constants (u = lane + 32s over 4 cols x 100 cells) ----
    int      acc[NUNIT];
    unsigned ad1[NUNIT], ad2[NUNIT], adc[NUNIT];
    bool     uval[NUNIT];
    #pragma unroll
    for (int s = 0; s < NUNIT; s++) {
        const int u  = lane + 32 * s;
        uval[s] = (u < 400);
        const int uu = uval[s] ? u : 0;
        const int q  = uu / 100;            // owned-col index 0..3
        const int r  = uu - q * 100;        // cell = i*10+j
        const int i  = r / 10;
        const int j  = r - i * 10;
        ad1[s] = w * MWARP + q * MROW + i;
        ad2[s] = w * MWARP + q * MROW + 10 + j;
        adc[s] = (4 * w + q) * CSTR + r;
        acc[s] = 0;
    }
    __syncthreads();

    // ---- Main loop over k-tiles ----
    for (int t = 0; t < NTILE; t++) {
        const int kb = k0 + t * TILE;

        // Stage (coalesced full 128B lines)
        for (int e = tid; e < TILE * 32; e += THREADS) {
            const int r = e >> 5;
            const int c = e & 31;
            s1[r * 33 + c] = __ldg(&idx1[(size_t)(kb + r) * B + b0 + c]);
            s2[r * 33 + c] = __ldg(&idx2[(size_t)(kb + r) * B + b0 + c]);
        }
        __syncthreads();

        // Build per-col masks: warp w, cols 4w..4w+3, k-per-lane (conflict-free)
        #pragma unroll
        for (int q = 0; q < 4; q++) {
            const int cb = 4 * w + q;
            const int i1 = s1[lane * 33 + cb];
            const int i2 = s2[lane * 33 + cb];

            const unsigned a0 = __ballot_sync(0xffffffffu, (i1 & 1) != 0);
            const unsigned a1 = __ballot_sync(0xffffffffu, (i1 & 2) != 0);
            const unsigned a2 = __ballot_sync(0xffffffffu, (i1 & 4) != 0);
            const unsigned a3 = __ballot_sync(0xffffffffu, (i1 & 8) != 0);
            const unsigned c0 = __ballot_sync(0xffffffffu, (i2 & 1) != 0);
            const unsigned c1 = __ballot_sync(0xffffffffu, (i2 & 2) != 0);
            const unsigned c2 = __ballot_sync(0xffffffffu, (i2 & 4) != 0);
            const unsigned c3 = __ballot_sync(0xffffffffu, (i2 & 8) != 0);

            // Lane L builds the mask of k's where idx == L (valid for L<10)
            const unsigned k1 = ((lane & 1) ? a0 : ~a0) & ((lane & 2) ? a1 : ~a1) &
                                ((lane & 4) ? a2 : ~a2) & ((lane & 8) ? a3 : ~a3);
            const unsigned k2 = ((lane & 1) ? c0 : ~c0) & ((lane & 2) ? c1 : ~c1) &
                                ((lane & 4) ? c2 : ~c2) & ((lane & 8) ? c3 : ~c3);
            if (lane < 10) {
                masks[w * MWARP + q * MROW + lane]      = k1;
                masks[w * MWARP + q * MROW + 10 + lane] = k2;
            }
        }
        __syncwarp();

        // Joint counts: 13 pair-units per lane into register accumulators
        #pragma unroll
        for (int s = 0; s < NUNIT; s++) {
            if (uval[s]) {
                acc[s] += __popc(masks[ad1[s]] & masks[ad2[s]]);
            }
        }
        __syncthreads();   // tile buffers + masks reused next iteration
    }

    // ---- Dump register counts (each (b,cell) has exactly one owner lane) ----
    #pragma unroll
    for (int s = 0; s < NUNIT; s++) {
        if (uval[s]) {
            cnt[adc[s]] = (unsigned)acc[s];
        }
    }
    __syncthreads();

    // ---- Epilogue: result[b][m] = sum_{i+j=m} xs1[i]*xs2[j]*cnt[i,j] ----
    for (int e = tid; e < NB * M; e += THREADS) {
        const int bl  = e & (NB - 1);
        const int m   = e >> 5;
        const int ilo = (m > 9) ? (m - 9) : 0;
        const int ihi = (m < 9) ? m : 9;
        float v = 0.0f;
        for (int i = ilo; i <= ihi; i++) {
            const int j = m - i;
            v += xs1[bl][i] * xs2[bl][j] *
                 (float)cnt[bl * CSTR + i * 10 + j];
        }
        atomicAdd(&g_scratch[(b0 + bl) * M + m], v);
    }

    // ---- Ticket: last KSPLIT-block for this row-group finishes the rows ----
    __threadfence();
    __syncthreads();
    if (tid == 0) {
        s_last = (atomicAdd(&g_ticket[blockIdx.x], 1) == KSPLIT - 1);
    }
    __syncthreads();
    if (!s_last) return;

    for (int e = tid; e < NB * M; e += THREADS) {
        const int bl = e & (NB - 1);
        const int m  = e >> 5;
        rowsum[bl][m] = __ldcg(&g_scratch[(b0 + bl) * M + m]);
    }
    __syncthreads();

    if (tid < NB) {
        float sq = 0.0f;
        #pragma unroll
        for (int m = 0; m < M; m++) {
            const float v = rowsum[tid][m];
            sq += v * v;
        }
        rowsum[tid][M] = 1.0f / fmaxf(sqrtf(sq), 1e-12f);
    }
    __syncthreads();

    for (int e = tid; e < NB * M; e += THREADS) {
        const int bl = e & (NB - 1);
        const int m  = e >> 5;
        out[(size_t)(b0 + bl) * M + m] = rowsum[bl][m] * rowsum[bl][M];
        __stcg(&g_scratch[(b0 + bl) * M + m], 0.0f);   // reset for next replay
    }
    if (tid == 0) {
        g_ticket[blockIdx.x] = 0;
    }
}

extern "C" void kernel_launch(void* const* d_in, const int* in_sizes, int n_in,
                              void* d_out, int out_size)
{
    const float* x1   = (const float*)d_in[0];   // [B, C]
    const float* x2   = (const float*)d_in[1];   // [B, C]
    const int*   idx1 = (const int*)d_in[2];     // [K, B]
    const int*   idx2 = (const int*)d_in[3];     // [K, B]
    float*       out  = (float*)d_out;           // [B, M]

    (void)in_sizes; (void)n_in; (void)out_size;

    dim3 grid(B / NB, KSPLIT);
    ised_kernel<<<grid, THREADS>>>(x1, x2, idx1, idx2, out);
}